// round 6
// baseline (speedup 1.0000x reference)
#include <cuda_runtime.h>
#include <math.h>

#define NPTS 32768
#define CIN  32
#define F0   256
#define KATT 1024
#define BSEG 16
#define KC   32768
#define EPAD 40
#define BN_EPS 1e-5f

#define TILE_N 64
#define ESTRIDE 76
/* k2 smem (floats): stages: sA[128][36]+sB[64][36] = 6912/stage, 2 stages = 13824
   epilogue alias:   sE[128][76] = 9728, sX[128][40] = 5120 -> 14848 floats  */
#define STAGE_FLOATS 6912
#define SMEM_FLOATS  14848

// ---------------- scratch ----------------
__device__ float g_att1[NPTS * F0];
__device__ float g_E[BSEG * KATT * EPAD];
__device__ float g_out2[BSEG * KC];
__device__ float g_rtmp[BSEG * F0];
__device__ float g_s1[F0], g_t1[F0];
__device__ float g_s2[KATT], g_t2[KATT];
__device__ float g_s3[F0], g_t3[F0];
__device__ int   g_off[BSEG + 1];

// ---------------- helpers ----------------
static __device__ __forceinline__ unsigned utf32(float x) {
    unsigned r;
    asm("cvt.rna.tf32.f32 %0, %1;" : "=r"(r) : "f"(x));
    return r;
}

static __device__ __forceinline__ void mma_tf32(float* d, const unsigned* a, const unsigned* b) {
    asm volatile(
        "mma.sync.aligned.m16n8k8.row.col.f32.tf32.tf32.f32 "
        "{%0,%1,%2,%3}, {%4,%5,%6,%7}, {%8,%9}, {%0,%1,%2,%3};\n"
        : "+f"(d[0]), "+f"(d[1]), "+f"(d[2]), "+f"(d[3])
        : "r"(a[0]), "r"(a[1]), "r"(a[2]), "r"(a[3]), "r"(b[0]), "r"(b[1]));
}

static __device__ __forceinline__ void cpa16(unsigned* s, const float* g) {
    unsigned sa = (unsigned)__cvta_generic_to_shared(s);
    asm volatile("cp.async.cg.shared.global [%0], [%1], 16;\n" :: "r"(sa), "l"(g));
}
#define CPA_COMMIT() asm volatile("cp.async.commit_group;\n" ::: "memory")
#define CPA_WAIT0()  asm volatile("cp.async.wait_group 0;\n" ::: "memory")

static __device__ __forceinline__ int seg_of(int row) {
    int s = 0;
    while (s < BSEG - 1 && row >= g_off[s + 1]) s++;
    return s;
}

// ---------------- k0 ----------------
__global__ void k0_prep(const int* __restrict__ len,
                        const float* __restrict__ b1, const float* __restrict__ g1,
                        const float* __restrict__ be1, const float* __restrict__ m1,
                        const float* __restrict__ v1,
                        const float* __restrict__ b2, const float* __restrict__ g2,
                        const float* __restrict__ be2, const float* __restrict__ m2,
                        const float* __restrict__ v2,
                        const float* __restrict__ fcb, const float* __restrict__ g3,
                        const float* __restrict__ be3, const float* __restrict__ m3,
                        const float* __restrict__ v3) {
    int t = threadIdx.x;
    if (t == 0) {
        int acc = 0;
        for (int i = 0; i < BSEG; i++) { g_off[i] = acc; acc += len[i]; }
        g_off[BSEG] = acc;
    }
    if (t < F0) {
        float a = g1[t] * rsqrtf(v1[t] + BN_EPS);
        g_s1[t] = a;
        g_t1[t] = (b1[t] - m1[t]) * a + be1[t];
        float a3 = g3[t] * rsqrtf(v3[t] + BN_EPS);
        g_s3[t] = a3;
        g_t3[t] = (fcb[t] - m3[t]) * a3 + be3[t];
    }
    {
        float a2 = g2[t] * rsqrtf(v2[t] + BN_EPS);
        g_s2[t] = a2;
        g_t2[t] = (b2[t] - m2[t]) * a2 + be2[t];
    }
}

__global__ void k0_zero() {
    int idx = blockIdx.x * 256 + threadIdx.x;
    if (idx < BSEG * KATT * EPAD) g_E[idx] = 0.f;
    if (idx < BSEG * F0) g_rtmp[idx] = 0.f;
}

// ---------------- k1: att1 = relu(bn1(x @ w1^T)) ----------------
__global__ __launch_bounds__(256) void k1_gemm1(const float* __restrict__ x,
                                                const float* __restrict__ w1) {
    __shared__ unsigned sA[128 * 36];
    __shared__ unsigned sB[128 * 36];
    int tid = threadIdx.x;
    int rowBase = blockIdx.x * 128;
    int colBase = blockIdx.y * 128;

#pragma unroll
    for (int i = 0; i < 16; i++) {
        int idx = tid + i * 256;
        int r = idx >> 5, c = idx & 31;
        sA[r * 36 + c] = utf32(x[(rowBase + r) * CIN + c]);
        sB[r * 36 + c] = utf32(w1[(colBase + r) * CIN + c]);
    }
    __syncthreads();

    int wid = tid >> 5, lane = tid & 31;
    int g = lane >> 2, tg = lane & 3;
    int wr = (wid & 1) * 64;
    int wc = (wid >> 1) * 32;
    float acc[4][4][4] = {};

#pragma unroll
    for (int ks = 0; ks < 32; ks += 8) {
        unsigned af[4][4], bf[4][2];
#pragma unroll
        for (int mt = 0; mt < 4; mt++) {
            int r0 = wr + mt * 16 + g;
            af[mt][0] = sA[r0 * 36 + ks + tg];
            af[mt][1] = sA[(r0 + 8) * 36 + ks + tg];
            af[mt][2] = sA[r0 * 36 + ks + tg + 4];
            af[mt][3] = sA[(r0 + 8) * 36 + ks + tg + 4];
        }
#pragma unroll
        for (int nt = 0; nt < 4; nt++) {
            int n0 = wc + nt * 8 + g;
            bf[nt][0] = sB[n0 * 36 + ks + tg];
            bf[nt][1] = sB[n0 * 36 + ks + tg + 4];
        }
#pragma unroll
        for (int mt = 0; mt < 4; mt++)
#pragma unroll
            for (int nt = 0; nt < 4; nt++) mma_tf32(acc[mt][nt], af[mt], bf[nt]);
    }

#pragma unroll
    for (int mt = 0; mt < 4; mt++) {
#pragma unroll
        for (int nt = 0; nt < 4; nt++) {
            int col = colBase + wc + nt * 8 + 2 * tg;
            float s0 = g_s1[col], t0 = g_t1[col];
            float s1v = g_s1[col + 1], t1v = g_t1[col + 1];
            int r0 = rowBase + wr + mt * 16 + g;
            float v0 = fmaxf(acc[mt][nt][0] * s0 + t0, 0.f);
            float v1 = fmaxf(acc[mt][nt][1] * s1v + t1v, 0.f);
            float v2 = fmaxf(acc[mt][nt][2] * s0 + t0, 0.f);
            float v3 = fmaxf(acc[mt][nt][3] * s1v + t1v, 0.f);
            *(float2*)&g_att1[r0 * F0 + col] = make_float2(v0, v1);
            *(float2*)&g_att1[(r0 + 8) * F0 + col] = make_float2(v2, v3);
        }
    }
}

// ---------------- k2: GEMM2 (128x64 tile, 3 CTAs/SM) + exp + e^T@x_aug ----------------
__global__ __launch_bounds__(256, 3) void k2_main(const float* __restrict__ x,
                                                  const float* __restrict__ w2) {
    extern __shared__ unsigned sm[];
    unsigned* sE = sm;               // [128][76] aliased after main loop
    unsigned* sX = sm + 128 * ESTRIDE;  // [128][40]

    int tid = threadIdx.x;
    int rowBase = blockIdx.x * 128;
    int colBase = blockIdx.y * TILE_N;
    int wid = tid >> 5, lane = tid & 31;
    int g = lane >> 2, tg = lane & 3;
    int wr = (wid & 3) * 32;          // 4 row groups
    int wc = (wid >> 2) * 32;         // 2 col groups
    float acc[2][4][4] = {};

    const float* gA = g_att1 + (long)rowBase * F0;
    const float* gB = w2 + (long)colBase * F0;

    // prologue: stage chunk 0
    {
        unsigned* sA = sm;
        unsigned* sB = sm + 128 * 36;
#pragma unroll
        for (int i = 0; i < 4; i++) {
            int u = tid + i * 256;    // 0..1023: A rows 128 x 8 units
            int r = u >> 3, cu = u & 7;
            cpa16(sA + r * 36 + cu * 4, gA + (long)r * F0 + cu * 4);
        }
#pragma unroll
        for (int i = 0; i < 2; i++) {
            int u = tid + i * 256;    // 0..511: B rows 64 x 8 units
            int r = u >> 3, cu = u & 7;
            cpa16(sB + r * 36 + cu * 4, gB + (long)r * F0 + cu * 4);
        }
        CPA_COMMIT();
    }

    for (int c = 0; c < 8; c++) {
        CPA_WAIT0();
        __syncthreads();              // chunk c visible; compute(c-1) done

        if (c + 1 < 8) {
            unsigned* sA = sm + ((c + 1) & 1) * STAGE_FLOATS;
            unsigned* sB = sA + 128 * 36;
            int kc = (c + 1) * 32;
#pragma unroll
            for (int i = 0; i < 4; i++) {
                int u = tid + i * 256;
                int r = u >> 3, cu = u & 7;
                cpa16(sA + r * 36 + cu * 4, gA + (long)r * F0 + kc + cu * 4);
            }
#pragma unroll
            for (int i = 0; i < 2; i++) {
                int u = tid + i * 256;
                int r = u >> 3, cu = u & 7;
                cpa16(sB + r * 36 + cu * 4, gB + (long)r * F0 + kc + cu * 4);
            }
            CPA_COMMIT();
        }

        unsigned* sA = sm + (c & 1) * STAGE_FLOATS;
        unsigned* sB = sA + 128 * 36;
#pragma unroll
        for (int ks = 0; ks < 32; ks += 8) {
            unsigned af[2][4], bf[4][2];
#pragma unroll
            for (int mt = 0; mt < 2; mt++) {
                int r0 = wr + mt * 16 + g;
                af[mt][0] = sA[r0 * 36 + ks + tg];
                af[mt][1] = sA[(r0 + 8) * 36 + ks + tg];
                af[mt][2] = sA[r0 * 36 + ks + tg + 4];
                af[mt][3] = sA[(r0 + 8) * 36 + ks + tg + 4];
            }
#pragma unroll
            for (int nt = 0; nt < 4; nt++) {
                int n0 = wc + nt * 8 + g;
                bf[nt][0] = sB[n0 * 36 + ks + tg];
                bf[nt][1] = sB[n0 * 36 + ks + tg + 4];
            }
#pragma unroll
            for (int mt = 0; mt < 2; mt++)
#pragma unroll
                for (int nt = 0; nt < 4; nt++) mma_tf32(acc[mt][nt], af[mt], bf[nt]);
        }
    }

    __syncthreads();  // all mma smem reads done before aliasing

    // e = exp(relu(bn2(acc)))  -> sE
#pragma unroll
    for (int mt = 0; mt < 2; mt++) {
#pragma unroll
        for (int nt = 0; nt < 4; nt++) {
            int col = wc + nt * 8 + 2 * tg;
            int colG = colBase + col;
            float s0 = g_s2[colG], t0 = g_t2[colG];
            float s1v = g_s2[colG + 1], t1v = g_t2[colG + 1];
            int r0 = wr + mt * 16 + g;
            float e0 = __expf(fmaxf(acc[mt][nt][0] * s0 + t0, 0.f));
            float e1 = __expf(fmaxf(acc[mt][nt][1] * s1v + t1v, 0.f));
            float e2 = __expf(fmaxf(acc[mt][nt][2] * s0 + t0, 0.f));
            float e3 = __expf(fmaxf(acc[mt][nt][3] * s1v + t1v, 0.f));
            sE[r0 * ESTRIDE + col] = utf32(e0);
            sE[r0 * ESTRIDE + col + 1] = utf32(e1);
            sE[(r0 + 8) * ESTRIDE + col] = utf32(e2);
            sE[(r0 + 8) * ESTRIDE + col + 1] = utf32(e3);
        }
    }

    // x_aug: [128][40], cols 0..31 = x, col 32 = 1, rest 0
#pragma unroll
    for (int i = 0; i < 20; i++) {
        int idx = tid + i * 256;
        int r = idx / 40, n = idx % 40;
        float v = (n < 32) ? x[(rowBase + r) * CIN + n] : (n == 32 ? 1.0f : 0.0f);
        sX[r * 40 + n] = utf32(v);
    }
    __syncthreads();

    // phase-2: 8 warps = 4 col-groups x 2 row-halves; atomics merge halves
    int mcol = (wid & 3) * 16;
    int rb = (wid >> 2) * 64;
    int s0 = seg_of(rowBase + rb), s1 = seg_of(rowBase + rb + 63);
    for (int s = s0; s <= s1; s++) {
        int lo = max(g_off[s] - rowBase, rb);
        int hi = min(g_off[s + 1] - rowBase, rb + 64);
        float ea[5][4] = {};
        for (int kk = (lo & ~7); kk < hi; kk += 8) {
            int r0 = kk + tg, r1 = kk + tg + 4;
            bool m0 = (r0 >= lo && r0 < hi);
            bool m1 = (r1 >= lo && r1 < hi);
            unsigned af[4];
            af[0] = m0 ? sE[r0 * ESTRIDE + mcol + g] : 0u;
            af[1] = m0 ? sE[r0 * ESTRIDE + mcol + g + 8] : 0u;
            af[2] = m1 ? sE[r1 * ESTRIDE + mcol + g] : 0u;
            af[3] = m1 ? sE[r1 * ESTRIDE + mcol + g + 8] : 0u;
#pragma unroll
            for (int nt = 0; nt < 5; nt++) {
                unsigned bf[2];
                bf[0] = sX[r0 * 40 + nt * 8 + g];
                bf[1] = sX[r1 * 40 + nt * 8 + g];
                mma_tf32(ea[nt], af, bf);
            }
        }
#pragma unroll
        for (int nt = 0; nt < 5; nt++) {
            int n = nt * 8 + 2 * tg;
            int ac0 = colBase + mcol + g;
            int ac1 = ac0 + 8;
            if (n <= 32) atomicAdd(&g_E[((long)s * KATT + ac0) * EPAD + n], ea[nt][0]);
            if (n + 1 <= 32) atomicAdd(&g_E[((long)s * KATT + ac0) * EPAD + n + 1], ea[nt][1]);
            if (n <= 32) atomicAdd(&g_E[((long)s * KATT + ac1) * EPAD + n], ea[nt][2]);
            if (n + 1 <= 32) atomicAdd(&g_E[((long)s * KATT + ac1) * EPAD + n + 1], ea[nt][3]);
        }
    }
}

// ---------------- k_out2 ----------------
__global__ void k_out2(const int* __restrict__ len) {
    int idx = blockIdx.x * 256 + threadIdx.x;
    int b = idx >> 15;
    int kc = idx & 32767;
    int k = kc >> 5, c = kc & 31;
    const float* Eb = &g_E[((long)b * KATT + k) * EPAD];
    float S = Eb[32];
    g_out2[idx] = Eb[c] / (S * (float)len[b]);
}

// ---------------- k3 ----------------
__global__ __launch_bounds__(256) void k3_fc(const float* __restrict__ fcw) {
    int wg = blockIdx.x * 8 + (threadIdx.x >> 5);
    int lane = threadIdx.x & 31;
    int jg = wg & 31;
    int slice = wg >> 5;
    int j0 = jg * 8;
    int base = slice * 1024;
    float acc[8][16] = {};
    for (int it = 0; it < 32; it++) {
        int kc = base + it * 32 + lane;
        float w[8];
#pragma unroll
        for (int jj = 0; jj < 8; jj++) w[jj] = fcw[(long)(j0 + jj) * KC + kc];
#pragma unroll
        for (int bb = 0; bb < 16; bb++) {
            float o = g_out2[bb * KC + kc];
#pragma unroll
            for (int jj = 0; jj < 8; jj++) acc[jj][bb] = fmaf(o, w[jj], acc[jj][bb]);
        }
    }
#pragma unroll
    for (int jj = 0; jj < 8; jj++) {
#pragma unroll
        for (int bb = 0; bb < 16; bb++) {
            float v = acc[jj][bb];
            v += __shfl_down_sync(0xffffffffu, v, 16);
            v += __shfl_down_sync(0xffffffffu, v, 8);
            v += __shfl_down_sync(0xffffffffu, v, 4);
            v += __shfl_down_sync(0xffffffffu, v, 2);
            v += __shfl_down_sync(0xffffffffu, v, 1);
            if (lane == 0) atomicAdd(&g_rtmp[bb * F0 + j0 + jj], v);
        }
    }
}

// ---------------- k4 ----------------
__global__ void k4_norm(float* __restrict__ out) {
    int b = blockIdx.x;
    int j = threadIdx.x;
    float v = g_rtmp[b * F0 + j] * g_s3[j] + g_t3[j];
    __shared__ float red[256];
    red[j] = v * v;
    __syncthreads();
    for (int o = 128; o > 0; o >>= 1) {
        if (j < o) red[j] += red[j + o];
        __syncthreads();
    }
    float nrm = fmaxf(sqrtf(red[0]), 1e-12f);
    out[b * F0 + j] = v / nrm;
}

// ---------------- launch ----------------
extern "C" void kernel_launch(void* const* d_in, const int* in_sizes, int n_in,
                              void* d_out, int out_size) {
    const float* x   = (const float*)d_in[0];
    const int*   len = (const int*)d_in[1];
    const float* w1  = (const float*)d_in[2];
    const float* b1  = (const float*)d_in[3];
    const float* g1  = (const float*)d_in[4];
    const float* be1 = (const float*)d_in[5];
    const float* m1  = (const float*)d_in[6];
    const float* v1  = (const float*)d_in[7];
    const float* w2  = (const float*)d_in[8];
    const float* b2  = (const float*)d_in[9];
    const float* g2  = (const float*)d_in[10];
    const float* be2 = (const float*)d_in[11];
    const float* m2  = (const float*)d_in[12];
    const float* v2  = (const float*)d_in[13];
    const float* fcw = (const float*)d_in[14];
    const float* fcb = (const float*)d_in[15];
    const float* g3  = (const float*)d_in[16];
    const float* be3 = (const float*)d_in[17];
    const float* m3  = (const float*)d_in[18];
    const float* v3  = (const float*)d_in[19];
    float* out = (float*)d_out;

    const int k2_smem = SMEM_FLOATS * 4;  // 59392 B -> 3 CTAs/SM
    cudaFuncSetAttribute(k2_main, cudaFuncAttributeMaxDynamicSharedMemorySize, k2_smem);

    k0_prep<<<1, 1024>>>(len, b1, g1, be1, m1, v1, b2, g2, be2, m2, v2,
                         fcb, g3, be3, m3, v3);
    k0_zero<<<(BSEG * KATT * EPAD + 255) / 256, 256>>>();
    k1_gemm1<<<dim3(NPTS / 128, F0 / 128), 256>>>(x, w1);
    k2_main<<<dim3(NPTS / 128, KATT / TILE_N), 256, k2_smem>>>(x, w2);
    k_out2<<<(BSEG * KC) / 256, 256>>>(len);
    k3_fc<<<128, 256>>>(fcw);
    k4_norm<<<BSEG, 256>>>(out);
}

// round 7
// speedup vs baseline: 1.3996x; 1.3996x over previous
#include <cuda_runtime.h>
#include <cuda_bf16.h>
#include <math.h>

#define NPTS 32768
#define CIN  32
#define F0   256
#define KATT 1024
#define BSEG 16
#define KC   32768
#define EPAD 40
#define BN_EPS 1e-5f

#define TILE_N 128
#define SETU 68            /* uint stride of sEt row (128 pts bf16 + pad)   */
#define SETB 136           /* bf16 stride of sEt row                        */
#define SXTU 68            /* uint stride of sXt row                        */
#define STAGE_U (128 * 36 * 2)   /* uints per stage: A[128][36]+B[128][36] */
#define SMEM_U  (2 * STAGE_U)    /* 36864 uints = 73728 B                  */

// ---------------- scratch ----------------
__device__ unsigned g_att1b[NPTS * 128];   // bf16x2-packed att1, 16.8 MB
__device__ unsigned g_w2b[KATT * 128];     // bf16x2-packed w2, 512 KB
__device__ float g_E[BSEG * KATT * EPAD];
__device__ float g_out2[BSEG * KC];
__device__ float g_rtmp[BSEG * F0];
__device__ float g_s1[F0], g_t1[F0];
__device__ float g_s2[KATT], g_t2[KATT];
__device__ float g_s3[F0], g_t3[F0];
__device__ int   g_off[BSEG + 1];

// ---------------- helpers ----------------
static __device__ __forceinline__ unsigned utf32(float x) {
    unsigned r;
    asm("cvt.rna.tf32.f32 %0, %1;" : "=r"(r) : "f"(x));
    return r;
}

static __device__ __forceinline__ unsigned packbf(float lo, float hi) {
    unsigned r;
    asm("cvt.rn.bf16x2.f32 %0, %1, %2;" : "=r"(r) : "f"(hi), "f"(lo));
    return r;
}

static __device__ __forceinline__ void mma_tf32(float* d, const unsigned* a, const unsigned* b) {
    asm volatile(
        "mma.sync.aligned.m16n8k8.row.col.f32.tf32.tf32.f32 "
        "{%0,%1,%2,%3}, {%4,%5,%6,%7}, {%8,%9}, {%0,%1,%2,%3};\n"
        : "+f"(d[0]), "+f"(d[1]), "+f"(d[2]), "+f"(d[3])
        : "r"(a[0]), "r"(a[1]), "r"(a[2]), "r"(a[3]), "r"(b[0]), "r"(b[1]));
}

static __device__ __forceinline__ void mma_bf16(float* d, const unsigned* a, const unsigned* b) {
    asm volatile(
        "mma.sync.aligned.m16n8k16.row.col.f32.bf16.bf16.f32 "
        "{%0,%1,%2,%3}, {%4,%5,%6,%7}, {%8,%9}, {%0,%1,%2,%3};\n"
        : "+f"(d[0]), "+f"(d[1]), "+f"(d[2]), "+f"(d[3])
        : "r"(a[0]), "r"(a[1]), "r"(a[2]), "r"(a[3]), "r"(b[0]), "r"(b[1]));
}

static __device__ __forceinline__ void cpa16(void* s, const void* g) {
    unsigned sa = (unsigned)__cvta_generic_to_shared(s);
    asm volatile("cp.async.cg.shared.global [%0], [%1], 16;\n" :: "r"(sa), "l"(g));
}
#define CPA_COMMIT() asm volatile("cp.async.commit_group;\n" ::: "memory")
#define CPA_WAIT0()  asm volatile("cp.async.wait_group 0;\n" ::: "memory")

static __device__ __forceinline__ int seg_of(int row) {
    int s = 0;
    while (s < BSEG - 1 && row >= g_off[s + 1]) s++;
    return s;
}

// ---------------- k0_prep ----------------
__global__ void k0_prep(const int* __restrict__ len,
                        const float* __restrict__ b1, const float* __restrict__ g1,
                        const float* __restrict__ be1, const float* __restrict__ m1,
                        const float* __restrict__ v1,
                        const float* __restrict__ b2, const float* __restrict__ g2,
                        const float* __restrict__ be2, const float* __restrict__ m2,
                        const float* __restrict__ v2,
                        const float* __restrict__ fcb, const float* __restrict__ g3,
                        const float* __restrict__ be3, const float* __restrict__ m3,
                        const float* __restrict__ v3) {
    int t = threadIdx.x;
    if (t == 0) {
        int acc = 0;
        for (int i = 0; i < BSEG; i++) { g_off[i] = acc; acc += len[i]; }
        g_off[BSEG] = acc;
    }
    if (t < F0) {
        float a = g1[t] * rsqrtf(v1[t] + BN_EPS);
        g_s1[t] = a;
        g_t1[t] = (b1[t] - m1[t]) * a + be1[t];
        float a3 = g3[t] * rsqrtf(v3[t] + BN_EPS);
        g_s3[t] = a3;
        g_t3[t] = (fcb[t] - m3[t]) * a3 + be3[t];
    }
    {
        float a2 = g2[t] * rsqrtf(v2[t] + BN_EPS);
        g_s2[t] = a2;
        g_t2[t] = (b2[t] - m2[t]) * a2 + be2[t];
    }
}

// ---------------- k0_zero: zero E/rtmp + convert w2 -> bf16x2 ----------------
__global__ void k0_zero(const float* __restrict__ w2) {
    int idx = blockIdx.x * 256 + threadIdx.x;   // grid covers 655360
    if (idx < BSEG * KATT * EPAD) g_E[idx] = 0.f;
    if (idx < BSEG * F0) g_rtmp[idx] = 0.f;
    if (idx < KATT * 128) {
        int n = idx >> 7, p = idx & 127;
        g_w2b[idx] = packbf(w2[n * F0 + 2 * p], w2[n * F0 + 2 * p + 1]);
    }
}

// ---------------- k1: att1 = relu(bn1(x @ w1^T)) -> bf16 ----------------
__global__ __launch_bounds__(256) void k1_gemm1(const float* __restrict__ x,
                                                const float* __restrict__ w1) {
    __shared__ unsigned sA[128 * 36];
    __shared__ unsigned sB[128 * 36];
    int tid = threadIdx.x;
    int rowBase = blockIdx.x * 128;
    int colBase = blockIdx.y * 128;

#pragma unroll
    for (int i = 0; i < 16; i++) {
        int idx = tid + i * 256;
        int r = idx >> 5, c = idx & 31;
        sA[r * 36 + c] = utf32(x[(rowBase + r) * CIN + c]);
        sB[r * 36 + c] = utf32(w1[(colBase + r) * CIN + c]);
    }
    __syncthreads();

    int wid = tid >> 5, lane = tid & 31;
    int g = lane >> 2, tg = lane & 3;
    int wr = (wid & 1) * 64;
    int wc = (wid >> 1) * 32;
    float acc[4][4][4] = {};

#pragma unroll
    for (int ks = 0; ks < 32; ks += 8) {
        unsigned af[4][4], bf[4][2];
#pragma unroll
        for (int mt = 0; mt < 4; mt++) {
            int r0 = wr + mt * 16 + g;
            af[mt][0] = sA[r0 * 36 + ks + tg];
            af[mt][1] = sA[(r0 + 8) * 36 + ks + tg];
            af[mt][2] = sA[r0 * 36 + ks + tg + 4];
            af[mt][3] = sA[(r0 + 8) * 36 + ks + tg + 4];
        }
#pragma unroll
        for (int nt = 0; nt < 4; nt++) {
            int n0 = wc + nt * 8 + g;
            bf[nt][0] = sB[n0 * 36 + ks + tg];
            bf[nt][1] = sB[n0 * 36 + ks + tg + 4];
        }
#pragma unroll
        for (int mt = 0; mt < 4; mt++)
#pragma unroll
            for (int nt = 0; nt < 4; nt++) mma_tf32(acc[mt][nt], af[mt], bf[nt]);
    }

#pragma unroll
    for (int mt = 0; mt < 4; mt++) {
#pragma unroll
        for (int nt = 0; nt < 4; nt++) {
            int col = colBase + wc + nt * 8 + 2 * tg;   // even
            float s0 = g_s1[col], t0 = g_t1[col];
            float s1v = g_s1[col + 1], t1v = g_t1[col + 1];
            int r0 = rowBase + wr + mt * 16 + g;
            float v0 = fmaxf(acc[mt][nt][0] * s0 + t0, 0.f);
            float v1 = fmaxf(acc[mt][nt][1] * s1v + t1v, 0.f);
            float v2 = fmaxf(acc[mt][nt][2] * s0 + t0, 0.f);
            float v3 = fmaxf(acc[mt][nt][3] * s1v + t1v, 0.f);
            g_att1b[r0 * 128 + (col >> 1)] = packbf(v0, v1);
            g_att1b[(r0 + 8) * 128 + (col >> 1)] = packbf(v2, v3);
        }
    }
}

// ---------------- k2: bf16 GEMM2 (128x128 tile) + exp + e^T@x_aug ----------------
__global__ __launch_bounds__(256, 2) void k2_main(const float* __restrict__ x,
                                                  const float* __restrict__ w2unused) {
    extern __shared__ unsigned sm[];
    unsigned* sEtU = sm;                 // [128 attcols][68] (bf16 pts, transposed), aliased
    unsigned* sXtU = sm + 128 * SETU;    // [40][68]

    int tid = threadIdx.x;
    int rowBase = blockIdx.x * 128;
    int colBase = blockIdx.y * TILE_N;
    int wid = tid >> 5, lane = tid & 31;
    int g = lane >> 2, tg = lane & 3;
    int wr = (wid & 1) * 64;
    int wc = (wid >> 1) * 32;
    float acc[4][4][4] = {};

    const unsigned* gA = g_att1b + (long)rowBase * 128;
    const unsigned* gB = g_w2b + (long)colBase * 128;

    // prologue: stage chunk 0 (k 0..63 -> uints 0..31 of each row)
    {
        unsigned* sA = sm;
        unsigned* sB = sm + 128 * 36;
#pragma unroll
        for (int i = 0; i < 4; i++) {
            int u = tid + i * 256;      // 1024 units: 128 rows x 8 x 16B
            int r = u >> 3, cu = u & 7;
            cpa16(sA + r * 36 + cu * 4, gA + (long)r * 128 + cu * 4);
        }
#pragma unroll
        for (int i = 0; i < 4; i++) {
            int u = tid + i * 256;
            int r = u >> 3, cu = u & 7;
            cpa16(sB + r * 36 + cu * 4, gB + (long)r * 128 + cu * 4);
        }
        CPA_COMMIT();
    }

    for (int c = 0; c < 4; c++) {
        CPA_WAIT0();
        __syncthreads();               // chunk c visible; compute(c-1) done

        if (c + 1 < 4) {
            unsigned* sA = sm + ((c + 1) & 1) * STAGE_U;
            unsigned* sB = sA + 128 * 36;
            int ku = (c + 1) * 32;     // uint offset of chunk in row
#pragma unroll
            for (int i = 0; i < 4; i++) {
                int u = tid + i * 256;
                int r = u >> 3, cu = u & 7;
                cpa16(sA + r * 36 + cu * 4, gA + (long)r * 128 + ku + cu * 4);
            }
#pragma unroll
            for (int i = 0; i < 4; i++) {
                int u = tid + i * 256;
                int r = u >> 3, cu = u & 7;
                cpa16(sB + r * 36 + cu * 4, gB + (long)r * 128 + ku + cu * 4);
            }
            CPA_COMMIT();
        }

        unsigned* sA = sm + (c & 1) * STAGE_U;
        unsigned* sB = sA + 128 * 36;
#pragma unroll
        for (int j = 0; j < 4; j++) {  // k16 per iter
            unsigned af[4][4], bf[4][2];
#pragma unroll
            for (int mt = 0; mt < 4; mt++) {
                int r0 = wr + mt * 16 + g;
                af[mt][0] = sA[r0 * 36 + j * 8 + tg];
                af[mt][1] = sA[(r0 + 8) * 36 + j * 8 + tg];
                af[mt][2] = sA[r0 * 36 + j * 8 + tg + 4];
                af[mt][3] = sA[(r0 + 8) * 36 + j * 8 + tg + 4];
            }
#pragma unroll
            for (int nt = 0; nt < 4; nt++) {
                int n0 = wc + nt * 8 + g;
                bf[nt][0] = sB[n0 * 36 + j * 8 + tg];
                bf[nt][1] = sB[n0 * 36 + j * 8 + tg + 4];
            }
#pragma unroll
            for (int mt = 0; mt < 4; mt++)
#pragma unroll
                for (int nt = 0; nt < 4; nt++) mma_bf16(acc[mt][nt], af[mt], bf[nt]);
        }
    }

    __syncthreads();   // all mma smem reads done before aliasing

    // epilogue: e = exp(relu(bn2(acc))) -> sEt (transposed, bf16)
    __nv_bfloat16* sEtB = (__nv_bfloat16*)sEtU;
#pragma unroll
    for (int mt = 0; mt < 4; mt++) {
#pragma unroll
        for (int nt = 0; nt < 4; nt++) {
            int col = wc + nt * 8 + 2 * tg;
            int colG = colBase + col;
            float s0 = g_s2[colG], t0 = g_t2[colG];
            float s1v = g_s2[colG + 1], t1v = g_t2[colG + 1];
            int r0 = wr + mt * 16 + g;
            float e0 = __expf(fmaxf(acc[mt][nt][0] * s0 + t0, 0.f));
            float e1 = __expf(fmaxf(acc[mt][nt][1] * s1v + t1v, 0.f));
            float e2 = __expf(fmaxf(acc[mt][nt][2] * s0 + t0, 0.f));
            float e3 = __expf(fmaxf(acc[mt][nt][3] * s1v + t1v, 0.f));
            sEtB[col * SETB + r0] = __float2bfloat16_rn(e0);
            sEtB[(col + 1) * SETB + r0] = __float2bfloat16_rn(e1);
            sEtB[col * SETB + r0 + 8] = __float2bfloat16_rn(e2);
            sEtB[(col + 1) * SETB + r0 + 8] = __float2bfloat16_rn(e3);
        }
    }

    // x_aug transposed: sXt[n][pt-pairs], n 0..39 (32=ones, 33-39 zero)
#pragma unroll
    for (int i = 0; i < 10; i++) {
        int idx = tid + i * 256;       // < 2560 = 40 x 64
        int n = idx >> 6, pp = idx & 63;
        float lo, hi;
        if (n < 32) {
            lo = x[(long)(rowBase + 2 * pp) * CIN + n];
            hi = x[(long)(rowBase + 2 * pp + 1) * CIN + n];
        } else if (n == 32) { lo = hi = 1.f; }
        else { lo = hi = 0.f; }
        sXtU[n * SXTU + pp] = packbf(lo, hi);
    }
    __syncthreads();

    // phase-2: per-segment e^T @ x_aug (bf16 m16n8k16, 16 pts per iter)
    int s0 = seg_of(rowBase), s1 = seg_of(rowBase + 127);
    int mcol = wid * 16;
    for (int s = s0; s <= s1; s++) {
        int lo = max(g_off[s] - rowBase, 0);
        int hi = min(g_off[s + 1] - rowBase, 128);
        float ea[5][4] = {};
        for (int kk = (lo & ~15); kk < hi; kk += 16) {
            int pA = kk + 2 * tg;       // pts pA, pA+1
            int pB = pA + 8;            // pts pB, pB+1
            unsigned maskA = ((pA >= lo && pA < hi) ? 0x0000FFFFu : 0u) |
                             ((pA + 1 >= lo && pA + 1 < hi) ? 0xFFFF0000u : 0u);
            unsigned maskB = ((pB >= lo && pB < hi) ? 0x0000FFFFu : 0u) |
                             ((pB + 1 >= lo && pB + 1 < hi) ? 0xFFFF0000u : 0u);
            int ub = (kk >> 1) + tg;
            unsigned af[4];
            af[0] = sEtU[(mcol + g) * SETU + ub] & maskA;
            af[1] = sEtU[(mcol + g + 8) * SETU + ub] & maskA;
            af[2] = sEtU[(mcol + g) * SETU + ub + 4] & maskB;
            af[3] = sEtU[(mcol + g + 8) * SETU + ub + 4] & maskB;
#pragma unroll
            for (int nt = 0; nt < 5; nt++) {
                unsigned bf[2];
                bf[0] = sXtU[(nt * 8 + g) * SXTU + ub];
                bf[1] = sXtU[(nt * 8 + g) * SXTU + ub + 4];
                mma_bf16(ea[nt], af, bf);
            }
        }
#pragma unroll
        for (int nt = 0; nt < 5; nt++) {
            int n = nt * 8 + 2 * tg;
            int ac0 = colBase + mcol + g;
            int ac1 = ac0 + 8;
            if (n <= 32) atomicAdd(&g_E[((long)s * KATT + ac0) * EPAD + n], ea[nt][0]);
            if (n + 1 <= 32) atomicAdd(&g_E[((long)s * KATT + ac0) * EPAD + n + 1], ea[nt][1]);
            if (n <= 32) atomicAdd(&g_E[((long)s * KATT + ac1) * EPAD + n], ea[nt][2]);
            if (n + 1 <= 32) atomicAdd(&g_E[((long)s * KATT + ac1) * EPAD + n + 1], ea[nt][3]);
        }
    }
}

// ---------------- k_out2: warp per (b,k) ----------------
__global__ void k_out2(const int* __restrict__ len) {
    int bk = blockIdx.x * 8 + (threadIdx.x >> 5);  // 16384
    int lane = threadIdx.x & 31;
    int b = bk >> 10, k = bk & 1023;
    const float* Eb = &g_E[(long)bk * EPAD];
    float rcp = 1.f / (Eb[32] * (float)len[b]);
    g_out2[((long)b << 15) + (k << 5) + lane] = Eb[lane] * rcp;
}

// ---------------- k3 ----------------
__global__ __launch_bounds__(256) void k3_fc(const float* __restrict__ fcw) {
    int wg = blockIdx.x * 8 + (threadIdx.x >> 5);
    int lane = threadIdx.x & 31;
    int jg = wg & 31;
    int slice = wg >> 5;
    int j0 = jg * 8;
    int base = slice * 1024;
    float acc[8][16] = {};
    for (int it = 0; it < 32; it++) {
        int kc = base + it * 32 + lane;
        float w[8];
#pragma unroll
        for (int jj = 0; jj < 8; jj++) w[jj] = fcw[(long)(j0 + jj) * KC + kc];
#pragma unroll
        for (int bb = 0; bb < 16; bb++) {
            float o = g_out2[bb * KC + kc];
#pragma unroll
            for (int jj = 0; jj < 8; jj++) acc[jj][bb] = fmaf(o, w[jj], acc[jj][bb]);
        }
    }
#pragma unroll
    for (int jj = 0; jj < 8; jj++) {
#pragma unroll
        for (int bb = 0; bb < 16; bb++) {
            float v = acc[jj][bb];
            v += __shfl_down_sync(0xffffffffu, v, 16);
            v += __shfl_down_sync(0xffffffffu, v, 8);
            v += __shfl_down_sync(0xffffffffu, v, 4);
            v += __shfl_down_sync(0xffffffffu, v, 2);
            v += __shfl_down_sync(0xffffffffu, v, 1);
            if (lane == 0) atomicAdd(&g_rtmp[bb * F0 + j0 + jj], v);
        }
    }
}

// ---------------- k4 ----------------
__global__ void k4_norm(float* __restrict__ out) {
    int b = blockIdx.x;
    int j = threadIdx.x;
    float v = g_rtmp[b * F0 + j] * g_s3[j] + g_t3[j];
    __shared__ float red[256];
    red[j] = v * v;
    __syncthreads();
    for (int o = 128; o > 0; o >>= 1) {
        if (j < o) red[j] += red[j + o];
        __syncthreads();
    }
    float nrm = fmaxf(sqrtf(red[0]), 1e-12f);
    out[b * F0 + j] = v / nrm;
}

// ---------------- launch ----------------
extern "C" void kernel_launch(void* const* d_in, const int* in_sizes, int n_in,
                              void* d_out, int out_size) {
    const float* x   = (const float*)d_in[0];
    const int*   len = (const int*)d_in[1];
    const float* w1  = (const float*)d_in[2];
    const float* b1  = (const float*)d_in[3];
    const float* g1  = (const float*)d_in[4];
    const float* be1 = (const float*)d_in[5];
    const float* m1  = (const float*)d_in[6];
    const float* v1  = (const float*)d_in[7];
    const float* w2  = (const float*)d_in[8];
    const float* b2  = (const float*)d_in[9];
    const float* g2  = (const float*)d_in[10];
    const float* be2 = (const float*)d_in[11];
    const float* m2  = (const float*)d_in[12];
    const float* v2  = (const float*)d_in[13];
    const float* fcw = (const float*)d_in[14];
    const float* fcb = (const float*)d_in[15];
    const float* g3  = (const float*)d_in[16];
    const float* be3 = (const float*)d_in[17];
    const float* m3  = (const float*)d_in[18];
    const float* v3  = (const float*)d_in[19];
    float* out = (float*)d_out;

    const int k2_smem = SMEM_U * 4;   // 73728 B -> 2 CTAs/SM
    cudaFuncSetAttribute(k2_main, cudaFuncAttributeMaxDynamicSharedMemorySize, k2_smem);

    k0_prep<<<1, 1024>>>(len, b1, g1, be1, m1, v1, b2, g2, be2, m2, v2,
                         fcb, g3, be3, m3, v3);
    k0_zero<<<(BSEG * KATT * EPAD + 255) / 256, 256>>>(w2);
    k1_gemm1<<<dim3(NPTS / 128, F0 / 128), 256>>>(x, w1);
    k2_main<<<dim3(NPTS / 128, KATT / TILE_N), 256, k2_smem>>>(x, w2);
    k_out2<<<2048, 256>>>(len);
    k3_fc<<<128, 256>>>(fcw);
    k4_norm<<<BSEG, 256>>>(out);
}

// round 8
// speedup vs baseline: 1.4168x; 1.0123x over previous
#include <cuda_runtime.h>
#include <cuda_bf16.h>
#include <math.h>

#define NPTS 32768
#define CIN  32
#define F0   256
#define KATT 1024
#define BSEG 16
#define KC   32768
#define EPAD 40
#define BN_EPS 1e-5f

#define TILE_N 128
#define SETU 68            /* uint stride of sEt row (128 pts bf16 + pad)   */
#define SETB 136           /* bf16 stride of sEt row                        */
#define SXTU 68            /* uint stride of sXt row                        */
#define STAGE_U (128 * 36 * 2)   /* uints per stage: A[128][36]+B[128][36] */
#define SMEM_U  (2 * STAGE_U)    /* 36864 uints = 73728 B                  */

// ---------------- scratch ----------------
__device__ unsigned g_att1b[NPTS * 128];   // bf16x2-packed att1, 16.8 MB
__device__ unsigned g_w2b[KATT * 128];     // bf16x2-packed w2, 512 KB
__device__ float g_E[BSEG * KATT * EPAD];
__device__ float g_out2[BSEG * KC];
__device__ float g_rtmp[BSEG * F0];
__device__ float g_s1[F0], g_t1[F0];
__device__ float g_s2[KATT], g_t2[KATT];
__device__ float g_s3[F0], g_t3[F0];
__device__ int   g_off[BSEG + 1];

// ---------------- helpers ----------------
static __device__ __forceinline__ unsigned utf32(float x) {
    unsigned r;
    asm("cvt.rna.tf32.f32 %0, %1;" : "=r"(r) : "f"(x));
    return r;
}

static __device__ __forceinline__ unsigned packbf(float lo, float hi) {
    unsigned r;
    asm("cvt.rn.bf16x2.f32 %0, %1, %2;" : "=r"(r) : "f"(hi), "f"(lo));
    return r;
}

static __device__ __forceinline__ void mma_tf32(float* d, const unsigned* a, const unsigned* b) {
    asm volatile(
        "mma.sync.aligned.m16n8k8.row.col.f32.tf32.tf32.f32 "
        "{%0,%1,%2,%3}, {%4,%5,%6,%7}, {%8,%9}, {%0,%1,%2,%3};\n"
        : "+f"(d[0]), "+f"(d[1]), "+f"(d[2]), "+f"(d[3])
        : "r"(a[0]), "r"(a[1]), "r"(a[2]), "r"(a[3]), "r"(b[0]), "r"(b[1]));
}

static __device__ __forceinline__ void mma_bf16(float* d, const unsigned* a, const unsigned* b) {
    asm volatile(
        "mma.sync.aligned.m16n8k16.row.col.f32.bf16.bf16.f32 "
        "{%0,%1,%2,%3}, {%4,%5,%6,%7}, {%8,%9}, {%0,%1,%2,%3};\n"
        : "+f"(d[0]), "+f"(d[1]), "+f"(d[2]), "+f"(d[3])
        : "r"(a[0]), "r"(a[1]), "r"(a[2]), "r"(a[3]), "r"(b[0]), "r"(b[1]));
}

static __device__ __forceinline__ void ldsm4(unsigned& r0, unsigned& r1, unsigned& r2,
                                             unsigned& r3, unsigned a) {
    asm volatile("ldmatrix.sync.aligned.m8n8.x4.shared.b16 {%0,%1,%2,%3}, [%4];"
                 : "=r"(r0), "=r"(r1), "=r"(r2), "=r"(r3) : "r"(a));
}

static __device__ __forceinline__ void cpa16(void* s, const void* g) {
    unsigned sa = (unsigned)__cvta_generic_to_shared(s);
    asm volatile("cp.async.cg.shared.global [%0], [%1], 16;\n" :: "r"(sa), "l"(g));
}
#define CPA_COMMIT() asm volatile("cp.async.commit_group;\n" ::: "memory")
#define CPA_WAIT0()  asm volatile("cp.async.wait_group 0;\n" ::: "memory")

static __device__ __forceinline__ int seg_of(int row) {
    int s = 0;
    while (s < BSEG - 1 && row >= g_off[s + 1]) s++;
    return s;
}

// ---------------- k0_prep ----------------
__global__ void k0_prep(const int* __restrict__ len,
                        const float* __restrict__ b1, const float* __restrict__ g1,
                        const float* __restrict__ be1, const float* __restrict__ m1,
                        const float* __restrict__ v1,
                        const float* __restrict__ b2, const float* __restrict__ g2,
                        const float* __restrict__ be2, const float* __restrict__ m2,
                        const float* __restrict__ v2,
                        const float* __restrict__ fcb, const float* __restrict__ g3,
                        const float* __restrict__ be3, const float* __restrict__ m3,
                        const float* __restrict__ v3) {
    int t = threadIdx.x;
    if (t == 0) {
        int acc = 0;
        for (int i = 0; i < BSEG; i++) { g_off[i] = acc; acc += len[i]; }
        g_off[BSEG] = acc;
    }
    if (t < F0) {
        float a = g1[t] * rsqrtf(v1[t] + BN_EPS);
        g_s1[t] = a;
        g_t1[t] = (b1[t] - m1[t]) * a + be1[t];
        float a3 = g3[t] * rsqrtf(v3[t] + BN_EPS);
        g_s3[t] = a3;
        g_t3[t] = (fcb[t] - m3[t]) * a3 + be3[t];
    }
    {
        float a2 = g2[t] * rsqrtf(v2[t] + BN_EPS);
        g_s2[t] = a2;
        g_t2[t] = (b2[t] - m2[t]) * a2 + be2[t];
    }
}

// ---------------- k0_zero ----------------
__global__ void k0_zero(const float* __restrict__ w2) {
    int idx = blockIdx.x * 256 + threadIdx.x;
    if (idx < BSEG * KATT * EPAD) g_E[idx] = 0.f;
    if (idx < BSEG * F0) g_rtmp[idx] = 0.f;
    if (idx < KATT * 128) {
        int n = idx >> 7, p = idx & 127;
        g_w2b[idx] = packbf(w2[n * F0 + 2 * p], w2[n * F0 + 2 * p + 1]);
    }
}

// ---------------- k1: att1 = relu(bn1(x @ w1^T)) -> bf16 ----------------
__global__ __launch_bounds__(256) void k1_gemm1(const float* __restrict__ x,
                                                const float* __restrict__ w1) {
    __shared__ unsigned sA[128 * 36];
    __shared__ unsigned sB[128 * 36];
    int tid = threadIdx.x;
    int rowBase = blockIdx.x * 128;
    int colBase = blockIdx.y * 128;

#pragma unroll
    for (int i = 0; i < 16; i++) {
        int idx = tid + i * 256;
        int r = idx >> 5, c = idx & 31;
        sA[r * 36 + c] = utf32(x[(rowBase + r) * CIN + c]);
        sB[r * 36 + c] = utf32(w1[(colBase + r) * CIN + c]);
    }
    __syncthreads();

    int wid = tid >> 5, lane = tid & 31;
    int g = lane >> 2, tg = lane & 3;
    int wr = (wid & 1) * 64;
    int wc = (wid >> 1) * 32;
    float acc[4][4][4] = {};

#pragma unroll
    for (int ks = 0; ks < 32; ks += 8) {
        unsigned af[4][4], bf[4][2];
#pragma unroll
        for (int mt = 0; mt < 4; mt++) {
            int r0 = wr + mt * 16 + g;
            af[mt][0] = sA[r0 * 36 + ks + tg];
            af[mt][1] = sA[(r0 + 8) * 36 + ks + tg];
            af[mt][2] = sA[r0 * 36 + ks + tg + 4];
            af[mt][3] = sA[(r0 + 8) * 36 + ks + tg + 4];
        }
#pragma unroll
        for (int nt = 0; nt < 4; nt++) {
            int n0 = wc + nt * 8 + g;
            bf[nt][0] = sB[n0 * 36 + ks + tg];
            bf[nt][1] = sB[n0 * 36 + ks + tg + 4];
        }
#pragma unroll
        for (int mt = 0; mt < 4; mt++)
#pragma unroll
            for (int nt = 0; nt < 4; nt++) mma_tf32(acc[mt][nt], af[mt], bf[nt]);
    }

#pragma unroll
    for (int mt = 0; mt < 4; mt++) {
#pragma unroll
        for (int nt = 0; nt < 4; nt++) {
            int col = colBase + wc + nt * 8 + 2 * tg;
            float s0 = g_s1[col], t0 = g_t1[col];
            float s1v = g_s1[col + 1], t1v = g_t1[col + 1];
            int r0 = rowBase + wr + mt * 16 + g;
            float v0 = fmaxf(acc[mt][nt][0] * s0 + t0, 0.f);
            float v1 = fmaxf(acc[mt][nt][1] * s1v + t1v, 0.f);
            float v2 = fmaxf(acc[mt][nt][2] * s0 + t0, 0.f);
            float v3 = fmaxf(acc[mt][nt][3] * s1v + t1v, 0.f);
            g_att1b[r0 * 128 + (col >> 1)] = packbf(v0, v1);
            g_att1b[(r0 + 8) * 128 + (col >> 1)] = packbf(v2, v3);
        }
    }
}

// ---------------- k2: bf16 GEMM2 with ldmatrix frag loads + exp + e^T@x_aug ----------------
__global__ __launch_bounds__(256, 2) void k2_main(const float* __restrict__ x,
                                                  const float* __restrict__ w2unused) {
    extern __shared__ unsigned sm[];
    unsigned* sEtU = sm;                 // [128 attcols][68] transposed bf16 e, aliased
    unsigned* sXtU = sm + 128 * SETU;    // [40][68]

    int tid = threadIdx.x;
    int rowBase = blockIdx.x * 128;
    int colBase = blockIdx.y * TILE_N;
    int wid = tid >> 5, lane = tid & 31;
    int g = lane >> 2, tg = lane & 3;
    int wr = (wid & 1) * 64;
    int wc = (wid >> 1) * 32;
    float acc[4][4][4] = {};

    const unsigned* gA = g_att1b + (long)rowBase * 128;
    const unsigned* gB = g_w2b + (long)colBase * 128;

    unsigned smBase = (unsigned)__cvta_generic_to_shared(sm);

    // ldmatrix per-thread row/col offsets (see derivation in analysis)
    int aRowL = (lane & 7) + ((lane >> 3) & 1) * 8;   // + mt*16 + wr
    int aKoff = (lane >> 4) << 2;                     // uints
    int bRowL = (lane & 7) + ((lane >> 4) << 3);      // + p*16 + wc
    int bKoff = ((lane >> 3) & 1) << 2;               // uints

    // prologue: stage chunk 0 (k 0..63 -> uints 0..31 of each row)
    {
        unsigned* sA = sm;
        unsigned* sB = sm + 128 * 36;
#pragma unroll
        for (int i = 0; i < 4; i++) {
            int u = tid + i * 256;
            int r = u >> 3, cu = u & 7;
            cpa16(sA + r * 36 + cu * 4, gA + (long)r * 128 + cu * 4);
        }
#pragma unroll
        for (int i = 0; i < 4; i++) {
            int u = tid + i * 256;
            int r = u >> 3, cu = u & 7;
            cpa16(sB + r * 36 + cu * 4, gB + (long)r * 128 + cu * 4);
        }
        CPA_COMMIT();
    }

    for (int c = 0; c < 4; c++) {
        CPA_WAIT0();
        __syncthreads();

        if (c + 1 < 4) {
            unsigned* sA = sm + ((c + 1) & 1) * STAGE_U;
            unsigned* sB = sA + 128 * 36;
            int ku = (c + 1) * 32;
#pragma unroll
            for (int i = 0; i < 4; i++) {
                int u = tid + i * 256;
                int r = u >> 3, cu = u & 7;
                cpa16(sA + r * 36 + cu * 4, gA + (long)r * 128 + ku + cu * 4);
            }
#pragma unroll
            for (int i = 0; i < 4; i++) {
                int u = tid + i * 256;
                int r = u >> 3, cu = u & 7;
                cpa16(sB + r * 36 + cu * 4, gB + (long)r * 128 + ku + cu * 4);
            }
            CPA_COMMIT();
        }

        unsigned sAb = smBase + ((c & 1) * STAGE_U) * 4;
        unsigned sBb = sAb + 128 * 36 * 4;

        // per-thread byte addresses for this chunk (j adds 32 B per step)
        unsigned aAddr[4], bAddr[2];
#pragma unroll
        for (int mt = 0; mt < 4; mt++)
            aAddr[mt] = sAb + ((wr + mt * 16 + aRowL) * 36 + aKoff) * 4;
#pragma unroll
        for (int p = 0; p < 2; p++)
            bAddr[p] = sBb + ((wc + p * 16 + bRowL) * 36 + bKoff) * 4;

#pragma unroll
        for (int j = 0; j < 4; j++) {
            unsigned af[4][4], bf[4][2];
#pragma unroll
            for (int mt = 0; mt < 4; mt++)
                ldsm4(af[mt][0], af[mt][1], af[mt][2], af[mt][3], aAddr[mt] + j * 32);
#pragma unroll
            for (int p = 0; p < 2; p++)
                ldsm4(bf[2 * p][0], bf[2 * p][1], bf[2 * p + 1][0], bf[2 * p + 1][1],
                      bAddr[p] + j * 32);
#pragma unroll
            for (int mt = 0; mt < 4; mt++)
#pragma unroll
                for (int nt = 0; nt < 4; nt++) mma_bf16(acc[mt][nt], af[mt], bf[nt]);
        }
    }

    __syncthreads();   // all mma smem reads done before aliasing

    // epilogue: e = exp(relu(bn2(acc))) -> sEt (transposed, bf16)
    __nv_bfloat16* sEtB = (__nv_bfloat16*)sEtU;
#pragma unroll
    for (int mt = 0; mt < 4; mt++) {
#pragma unroll
        for (int nt = 0; nt < 4; nt++) {
            int col = wc + nt * 8 + 2 * tg;
            int colG = colBase + col;
            float s0 = g_s2[colG], t0 = g_t2[colG];
            float s1v = g_s2[colG + 1], t1v = g_t2[colG + 1];
            int r0 = wr + mt * 16 + g;
            float e0 = __expf(fmaxf(acc[mt][nt][0] * s0 + t0, 0.f));
            float e1 = __expf(fmaxf(acc[mt][nt][1] * s1v + t1v, 0.f));
            float e2 = __expf(fmaxf(acc[mt][nt][2] * s0 + t0, 0.f));
            float e3 = __expf(fmaxf(acc[mt][nt][3] * s1v + t1v, 0.f));
            sEtB[col * SETB + r0] = __float2bfloat16_rn(e0);
            sEtB[(col + 1) * SETB + r0] = __float2bfloat16_rn(e1);
            sEtB[col * SETB + r0 + 8] = __float2bfloat16_rn(e2);
            sEtB[(col + 1) * SETB + r0 + 8] = __float2bfloat16_rn(e3);
        }
    }

    // x_aug transposed: sXt[n][pt-pairs]
#pragma unroll
    for (int i = 0; i < 10; i++) {
        int idx = tid + i * 256;
        int n = idx >> 6, pp = idx & 63;
        float lo, hi;
        if (n < 32) {
            lo = x[(long)(rowBase + 2 * pp) * CIN + n];
            hi = x[(long)(rowBase + 2 * pp + 1) * CIN + n];
        } else if (n == 32) { lo = hi = 1.f; }
        else { lo = hi = 0.f; }
        sXtU[n * SXTU + pp] = packbf(lo, hi);
    }
    __syncthreads();

    // phase-2: per-segment e^T @ x_aug (bf16 m16n8k16, 16 pts per iter)
    int s0 = seg_of(rowBase), s1 = seg_of(rowBase + 127);
    int mcol = wid * 16;
    for (int s = s0; s <= s1; s++) {
        int lo = max(g_off[s] - rowBase, 0);
        int hi = min(g_off[s + 1] - rowBase, 128);
        float ea[5][4] = {};
        for (int kk = (lo & ~15); kk < hi; kk += 16) {
            int pA = kk + 2 * tg;
            int pB = pA + 8;
            unsigned maskA = ((pA >= lo && pA < hi) ? 0x0000FFFFu : 0u) |
                             ((pA + 1 >= lo && pA + 1 < hi) ? 0xFFFF0000u : 0u);
            unsigned maskB = ((pB >= lo && pB < hi) ? 0x0000FFFFu : 0u) |
                             ((pB + 1 >= lo && pB + 1 < hi) ? 0xFFFF0000u : 0u);
            int ub = (kk >> 1) + tg;
            unsigned af[4];
            af[0] = sEtU[(mcol + g) * SETU + ub] & maskA;
            af[1] = sEtU[(mcol + g + 8) * SETU + ub] & maskA;
            af[2] = sEtU[(mcol + g) * SETU + ub + 4] & maskB;
            af[3] = sEtU[(mcol + g + 8) * SETU + ub + 4] & maskB;
#pragma unroll
            for (int nt = 0; nt < 5; nt++) {
                unsigned bf[2];
                bf[0] = sXtU[(nt * 8 + g) * SXTU + ub];
                bf[1] = sXtU[(nt * 8 + g) * SXTU + ub + 4];
                mma_bf16(ea[nt], af, bf);
            }
        }
#pragma unroll
        for (int nt = 0; nt < 5; nt++) {
            int n = nt * 8 + 2 * tg;
            int ac0 = colBase + mcol + g;
            int ac1 = ac0 + 8;
            if (n <= 32) atomicAdd(&g_E[((long)s * KATT + ac0) * EPAD + n], ea[nt][0]);
            if (n + 1 <= 32) atomicAdd(&g_E[((long)s * KATT + ac0) * EPAD + n + 1], ea[nt][1]);
            if (n <= 32) atomicAdd(&g_E[((long)s * KATT + ac1) * EPAD + n], ea[nt][2]);
            if (n + 1 <= 32) atomicAdd(&g_E[((long)s * KATT + ac1) * EPAD + n + 1], ea[nt][3]);
        }
    }
}

// ---------------- k_out2: warp per (b,k) ----------------
__global__ void k_out2(const int* __restrict__ len) {
    int bk = blockIdx.x * 8 + (threadIdx.x >> 5);
    int lane = threadIdx.x & 31;
    int b = bk >> 10, k = bk & 1023;
    const float* Eb = &g_E[(long)bk * EPAD];
    float rcp = 1.f / (Eb[32] * (float)len[b]);
    g_out2[((long)b << 15) + (k << 5) + lane] = Eb[lane] * rcp;
}

// ---------------- k3 ----------------
__global__ __launch_bounds__(256) void k3_fc(const float* __restrict__ fcw) {
    int wg = blockIdx.x * 8 + (threadIdx.x >> 5);
    int lane = threadIdx.x & 31;
    int jg = wg & 31;
    int slice = wg >> 5;
    int j0 = jg * 8;
    int base = slice * 1024;
    float acc[8][16] = {};
    for (int it = 0; it < 32; it++) {
        int kc = base + it * 32 + lane;
        float w[8];
#pragma unroll
        for (int jj = 0; jj < 8; jj++) w[jj] = fcw[(long)(j0 + jj) * KC + kc];
#pragma unroll
        for (int bb = 0; bb < 16; bb++) {
            float o = g_out2[bb * KC + kc];
#pragma unroll
            for (int jj = 0; jj < 8; jj++) acc[jj][bb] = fmaf(o, w[jj], acc[jj][bb]);
        }
    }
#pragma unroll
    for (int jj = 0; jj < 8; jj++) {
#pragma unroll
        for (int bb = 0; bb < 16; bb++) {
            float v = acc[jj][bb];
            v += __shfl_down_sync(0xffffffffu, v, 16);
            v += __shfl_down_sync(0xffffffffu, v, 8);
            v += __shfl_down_sync(0xffffffffu, v, 4);
            v += __shfl_down_sync(0xffffffffu, v, 2);
            v += __shfl_down_sync(0xffffffffu, v, 1);
            if (lane == 0) atomicAdd(&g_rtmp[bb * F0 + j0 + jj], v);
        }
    }
}

// ---------------- k4 ----------------
__global__ void k4_norm(float* __restrict__ out) {
    int b = blockIdx.x;
    int j = threadIdx.x;
    float v = g_rtmp[b * F0 + j] * g_s3[j] + g_t3[j];
    __shared__ float red[256];
    red[j] = v * v;
    __syncthreads();
    for (int o = 128; o > 0; o >>= 1) {
        if (j < o) red[j] += red[j + o];
        __syncthreads();
    }
    float nrm = fmaxf(sqrtf(red[0]), 1e-12f);
    out[b * F0 + j] = v / nrm;
}

// ---------------- launch ----------------
extern "C" void kernel_launch(void* const* d_in, const int* in_sizes, int n_in,
                              void* d_out, int out_size) {
    const float* x   = (const float*)d_in[0];
    const int*   len = (const int*)d_in[1];
    const float* w1  = (const float*)d_in[2];
    const float* b1  = (const float*)d_in[3];
    const float* g1  = (const float*)d_in[4];
    const float* be1 = (const float*)d_in[5];
    const float* m1  = (const float*)d_in[6];
    const float* v1  = (const float*)d_in[7];
    const float* w2  = (const float*)d_in[8];
    const float* b2  = (const float*)d_in[9];
    const float* g2  = (const float*)d_in[10];
    const float* be2 = (const float*)d_in[11];
    const float* m2  = (const float*)d_in[12];
    const float* v2  = (const float*)d_in[13];
    const float* fcw = (const float*)d_in[14];
    const float* fcb = (const float*)d_in[15];
    const float* g3  = (const float*)d_in[16];
    const float* be3 = (const float*)d_in[17];
    const float* m3  = (const float*)d_in[18];
    const float* v3  = (const float*)d_in[19];
    float* out = (float*)d_out;

    const int k2_smem = SMEM_U * 4;   // 73728 B -> 2 CTAs/SM
    cudaFuncSetAttribute(k2_main, cudaFuncAttributeMaxDynamicSharedMemorySize, k2_smem);

    k0_prep<<<1, 1024>>>(len, b1, g1, be1, m1, v1, b2, g2, be2, m2, v2,
                         fcb, g3, be3, m3, v3);
    k0_zero<<<(BSEG * KATT * EPAD + 255) / 256, 256>>>(w2);
    k1_gemm1<<<dim3(NPTS / 128, F0 / 128), 256>>>(x, w1);
    k2_main<<<dim3(NPTS / 128, KATT / TILE_N), 256, k2_smem>>>(x, w2);
    k_out2<<<2048, 256>>>(len);
    k3_fc<<<128, 256>>>(fcw);
    k4_norm<<<BSEG, 256>>>(out);
}